// round 2
// baseline (speedup 1.0000x reference)
#include <cuda_runtime.h>
#include <math.h>

#define NLAYERS 12
#define ROWS    2048      // B*S
#define DIM     1024
#define NSAMP   2048
#define KNEG    5
#define VEC     (DIM/4)   // 256 float4 per row
#define INV_T   10.0f     // 1/0.1
#define EPSN    1e-8f

// Per-(l,n) log-ratio terms. Every slot is written every launch -> no zeroing needed.
__device__ float g_partial[NLAYERS * NSAMP];

__global__ __launch_bounds__(256, 4)
void mi_pairs_kernel(const float4* __restrict__ acts,
                     const int*    __restrict__ anchor_idx,
                     const int*    __restrict__ pos_idx,
                     const int*    __restrict__ neg_idx)
{
    const int n = blockIdx.x;          // sample
    const int l = blockIdx.y;          // layer
    const int t = threadIdx.x;         // 0..255

    const float4* __restrict__ base = acts + (size_t)l * ROWS * VEC;

    // Anchor chunk in registers (loaded once, reused for all 6 partners)
    const int ia = anchor_idx[n];
    const float4 av = base[(size_t)ia * VEC + t];

    float part[13];
    part[0] = av.x*av.x + av.y*av.y + av.z*av.z + av.w*av.w;   // ||a||^2

    int idxs[6];
    idxs[0] = pos_idx[n];
#pragma unroll
    for (int k = 0; k < KNEG; k++) idxs[1 + k] = neg_idx[n * KNEG + k];

#pragma unroll
    for (int j = 0; j < 6; j++) {
        const float4 bv = base[(size_t)idxs[j] * VEC + t];
        part[1 + 2*j] = av.x*bv.x + av.y*bv.y + av.z*bv.z + av.w*bv.w;  // a.b
        part[2 + 2*j] = bv.x*bv.x + bv.y*bv.y + bv.z*bv.z + bv.w*bv.w;  // ||b||^2
    }

    // Fused block reduction of 13 scalars: warp shuffle -> smem -> warp 0
    __shared__ float sm[8][13];
#pragma unroll
    for (int i = 0; i < 13; i++) {
        float v = part[i];
#pragma unroll
        for (int o = 16; o; o >>= 1) v += __shfl_xor_sync(0xffffffffu, v, o);
        if ((t & 31) == 0) sm[t >> 5][i] = v;
    }
    __syncthreads();

    if (t == 0) {
        float tot[13];
#pragma unroll
        for (int i = 0; i < 13; i++) {
            float s = 0.f;
#pragma unroll
            for (int w = 0; w < 8; w++) s += sm[w][i];
            tot[i] = s;
        }
        const float inv_a = 1.f / fmaxf(sqrtf(tot[0]), EPSN);
        float sims[6];
#pragma unroll
        for (int j = 0; j < 6; j++) {
            const float inv_b = 1.f / fmaxf(sqrtf(tot[2 + 2*j]), EPSN);
            sims[j] = tot[1 + 2*j] * inv_a * inv_b * INV_T;
        }
        // stable log( exp(ps) / (exp(ps)+sum exp(ns)) ) = ps - logsumexp(all 6)
        float m = sims[0];
#pragma unroll
        for (int j = 1; j < 6; j++) m = fmaxf(m, sims[j]);
        float se = 0.f;
#pragma unroll
        for (int j = 0; j < 6; j++) se += expf(sims[j] - m);
        g_partial[l * NSAMP + n] = sims[0] - m - logf(se);
    }
}

__global__ __launch_bounds__(1024)
void mi_reduce_kernel(float* __restrict__ out)
{
    const int t = threadIdx.x;
    float s = 0.f;
    for (int i = t; i < NLAYERS * NSAMP; i += 1024) s += g_partial[i];

    __shared__ float sm[32];
#pragma unroll
    for (int o = 16; o; o >>= 1) s += __shfl_xor_sync(0xffffffffu, s, o);
    if ((t & 31) == 0) sm[t >> 5] = s;
    __syncthreads();
    if (t < 32) {
        float v = sm[t];
#pragma unroll
        for (int o = 16; o; o >>= 1) v += __shfl_xor_sync(0xffffffffu, v, o);
        if (t == 0) out[0] = -v / (float)(NLAYERS * NSAMP);
    }
}

extern "C" void kernel_launch(void* const* d_in, const int* in_sizes, int n_in,
                              void* d_out, int out_size)
{
    const float4* acts = (const float4*)d_in[0];
    const int* anchor_idx = (const int*)d_in[1];
    const int* pos_idx    = (const int*)d_in[2];
    const int* neg_idx    = (const int*)d_in[3];
    float* out = (float*)d_out;

    dim3 grid(NSAMP, NLAYERS);
    mi_pairs_kernel<<<grid, 256>>>(acts, anchor_idx, pos_idx, neg_idx);
    mi_reduce_kernel<<<1, 1024>>>(out);
}

// round 3
// speedup vs baseline: 1.6000x; 1.6000x over previous
#include <cuda_runtime.h>
#include <math.h>

#define NLAYERS 12
#define ROWS    2048      // B*S
#define DIM     1024
#define NSAMP   2048
#define KNEG    5
#define VEC     (DIM/4)   // 256 float4 per row
#define INV_T   10.0f     // 1/0.1
#define EPSN    1e-8f
#define NPART   (NLAYERS * NSAMP)   // 24576
#define S1BLKS  24                  // stage-1 reduce blocks (24 * 1024 = 24576)

__device__ float g_partial[NPART];
__device__ float g_stage[S1BLKS];

// ---------------------------------------------------------------------------
// Pairs kernel: one CTA per (layer, sample). 128 threads; each thread owns
// two float4 chunks (t and t+128) of every row -> 4 warps, half the shuffle
// work of the 256-thread version, double per-warp MLP (14 outstanding LDG.128).
// ---------------------------------------------------------------------------
__global__ __launch_bounds__(128, 8)
void mi_pairs_kernel(const float4* __restrict__ acts,
                     const int*    __restrict__ anchor_idx,
                     const int*    __restrict__ pos_idx,
                     const int*    __restrict__ neg_idx)
{
    const int n = blockIdx.x;          // sample
    const int l = blockIdx.y;          // layer
    const int t = threadIdx.x;         // 0..127

    const float4* __restrict__ base = acts + (size_t)l * ROWS * VEC;

    const int ia = anchor_idx[n];
    const float4* __restrict__ rowA = base + (size_t)ia * VEC;
    const float4 a0 = rowA[t];
    const float4 a1 = rowA[t + 128];

    float part[13];
    part[0] = a0.x*a0.x + a0.y*a0.y + a0.z*a0.z + a0.w*a0.w
            + a1.x*a1.x + a1.y*a1.y + a1.z*a1.z + a1.w*a1.w;   // ||a||^2

    int idxs[6];
    idxs[0] = pos_idx[n];
#pragma unroll
    for (int k = 0; k < KNEG; k++) idxs[1 + k] = neg_idx[n * KNEG + k];

#pragma unroll
    for (int j = 0; j < 6; j++) {
        const float4* __restrict__ rowB = base + (size_t)idxs[j] * VEC;
        const float4 b0 = rowB[t];
        const float4 b1 = rowB[t + 128];
        part[1 + 2*j] = a0.x*b0.x + a0.y*b0.y + a0.z*b0.z + a0.w*b0.w
                      + a1.x*b1.x + a1.y*b1.y + a1.z*b1.z + a1.w*b1.w;   // a.b
        part[2 + 2*j] = b0.x*b0.x + b0.y*b0.y + b0.z*b0.z + b0.w*b0.w
                      + b1.x*b1.x + b1.y*b1.y + b1.z*b1.z + b1.w*b1.w;   // ||b||^2
    }

    // Block reduction of 13 scalars: butterfly within warp, smem across 4 warps
    __shared__ float sm[4][13];
#pragma unroll
    for (int i = 0; i < 13; i++) {
        float v = part[i];
#pragma unroll
        for (int o = 16; o; o >>= 1) v += __shfl_xor_sync(0xffffffffu, v, o);
        if ((t & 31) == 0) sm[t >> 5][i] = v;
    }
    __syncthreads();

    if (t == 0) {
        float tot[13];
#pragma unroll
        for (int i = 0; i < 13; i++)
            tot[i] = sm[0][i] + sm[1][i] + sm[2][i] + sm[3][i];

        const float inv_a = 1.f / fmaxf(sqrtf(tot[0]), EPSN);
        float sims[6];
#pragma unroll
        for (int j = 0; j < 6; j++) {
            const float inv_b = 1.f / fmaxf(sqrtf(tot[2 + 2*j]), EPSN);
            sims[j] = tot[1 + 2*j] * inv_a * inv_b * INV_T;
        }
        float m = sims[0];
#pragma unroll
        for (int j = 1; j < 6; j++) m = fmaxf(m, sims[j]);
        float se = 0.f;
#pragma unroll
        for (int j = 0; j < 6; j++) se += expf(sims[j] - m);
        g_partial[l * NSAMP + n] = sims[0] - m - logf(se);
    }
}

// ---------------------------------------------------------------------------
// Two-stage deterministic tail reduction (replaces 8.7us single-block version)
// ---------------------------------------------------------------------------
__global__ __launch_bounds__(1024)
void mi_reduce1_kernel()
{
    const int t = threadIdx.x;
    float s = g_partial[blockIdx.x * 1024 + t];

    __shared__ float sm[32];
#pragma unroll
    for (int o = 16; o; o >>= 1) s += __shfl_xor_sync(0xffffffffu, s, o);
    if ((t & 31) == 0) sm[t >> 5] = s;
    __syncthreads();
    if (t < 32) {
        float v = sm[t];
#pragma unroll
        for (int o = 16; o; o >>= 1) v += __shfl_xor_sync(0xffffffffu, v, o);
        if (t == 0) g_stage[blockIdx.x] = v;
    }
}

__global__ __launch_bounds__(32)
void mi_reduce2_kernel(float* __restrict__ out)
{
    const int t = threadIdx.x;
    float v = (t < S1BLKS) ? g_stage[t] : 0.f;
#pragma unroll
    for (int o = 16; o; o >>= 1) v += __shfl_xor_sync(0xffffffffu, v, o);
    if (t == 0) out[0] = -v / (float)NPART;
}

extern "C" void kernel_launch(void* const* d_in, const int* in_sizes, int n_in,
                              void* d_out, int out_size)
{
    const float4* acts = (const float4*)d_in[0];
    const int* anchor_idx = (const int*)d_in[1];
    const int* pos_idx    = (const int*)d_in[2];
    const int* neg_idx    = (const int*)d_in[3];
    float* out = (float*)d_out;

    dim3 grid(NSAMP, NLAYERS);
    mi_pairs_kernel<<<grid, 128>>>(acts, anchor_idx, pos_idx, neg_idx);
    mi_reduce1_kernel<<<S1BLKS, 1024>>>();
    mi_reduce2_kernel<<<1, 32>>>(out);
}

// round 4
// speedup vs baseline: 1.9186x; 1.1991x over previous
#include <cuda_runtime.h>
#include <cuda_fp16.h>
#include <math.h>

#define NLAYERS 12
#define ROWS    2048               // B*S
#define DIM     1024
#define NSAMP   2048
#define KNEG    5
#define VEC     (DIM/4)            // 256 float4 per row (fp32)
#define HVEC    (DIM/8)            // 128 uint4 per row (fp16, 8 halves each)
#define INV_T   10.0f              // 1/0.1
#define EPSN    1e-8f
#define NPART   (NLAYERS * NSAMP)  // 24576
#define S1BLKS  24

// 48 MB scratch: pre-normalized fp16 rows, element order preserved.
__device__ uint4 g_nrm[(size_t)NLAYERS * ROWS * HVEC];
__device__ float g_partial[NPART];
__device__ float g_stage[S1BLKS];

__device__ __forceinline__ __half2 u2h2(unsigned u) {
    __half2 h; *reinterpret_cast<unsigned*>(&h) = u; return h;
}
__device__ __forceinline__ unsigned h2u(__half2 h) {
    return *reinterpret_cast<unsigned*>(&h);
}

// ---------------------------------------------------------------------------
// Pass 1: per-row L2 normalize, fp32 -> fp16, fold 1/norm in.
// One CTA per row (l*ROWS + r), 128 threads, 2 float4 per thread.
// ---------------------------------------------------------------------------
__global__ __launch_bounds__(128)
void norm_kernel(const float4* __restrict__ acts)
{
    const int row = blockIdx.x;             // 0 .. NLAYERS*ROWS-1
    const int t   = threadIdx.x;            // 0..127

    const float4* __restrict__ rp = acts + (size_t)row * VEC;
    const float4 v0 = rp[t];
    const float4 v1 = rp[t + 128];

    float ss = v0.x*v0.x + v0.y*v0.y + v0.z*v0.z + v0.w*v0.w
             + v1.x*v1.x + v1.y*v1.y + v1.z*v1.z + v1.w*v1.w;

    __shared__ float sm[4];
    __shared__ float s_inv;
#pragma unroll
    for (int o = 16; o; o >>= 1) ss += __shfl_xor_sync(0xffffffffu, ss, o);
    if ((t & 31) == 0) sm[t >> 5] = ss;
    __syncthreads();
    if (t == 0)
        s_inv = 1.f / fmaxf(sqrtf(sm[0] + sm[1] + sm[2] + sm[3]), EPSN);
    __syncthreads();
    const float inv = s_inv;

    uint2* __restrict__ out = reinterpret_cast<uint2*>(g_nrm) + (size_t)row * 2 * HVEC;
    // elements 4t..4t+3  (uint2 index t)  and  512+4t..  (uint2 index 128+t)
    uint2 w0, w1;
    w0.x = h2u(__floats2half2_rn(v0.x * inv, v0.y * inv));
    w0.y = h2u(__floats2half2_rn(v0.z * inv, v0.w * inv));
    w1.x = h2u(__floats2half2_rn(v1.x * inv, v1.y * inv));
    w1.y = h2u(__floats2half2_rn(v1.z * inv, v1.w * inv));
    out[t]       = w0;
    out[t + 128] = w1;
}

// ---------------------------------------------------------------------------
// Pass 2: per-(l,n) contrastive term on pre-normalized fp16 rows.
// One CTA per (sample, layer), 128 threads, one uint4 (8 halves) per row each.
// ---------------------------------------------------------------------------
__global__ __launch_bounds__(128)
void mi_pairs_kernel(const int* __restrict__ anchor_idx,
                     const int* __restrict__ pos_idx,
                     const int* __restrict__ neg_idx)
{
    const int n = blockIdx.x;
    const int l = blockIdx.y;
    const int t = threadIdx.x;

    const uint4* __restrict__ base = g_nrm + (size_t)l * ROWS * HVEC;

    const uint4 a = base[(size_t)anchor_idx[n] * HVEC + t];
    const __half2 a0 = u2h2(a.x), a1 = u2h2(a.y), a2 = u2h2(a.z), a3 = u2h2(a.w);

    int idxs[6];
    idxs[0] = pos_idx[n];
#pragma unroll
    for (int k = 0; k < KNEG; k++) idxs[1 + k] = neg_idx[n * KNEG + k];

    float part[6];
#pragma unroll
    for (int j = 0; j < 6; j++) {
        const uint4 b = base[(size_t)idxs[j] * HVEC + t];
        __half2 acc = __floats2half2_rn(0.f, 0.f);
        acc = __hfma2(a0, u2h2(b.x), acc);
        acc = __hfma2(a1, u2h2(b.y), acc);
        acc = __hfma2(a2, u2h2(b.z), acc);
        acc = __hfma2(a3, u2h2(b.w), acc);
        const float2 f = __half22float2(acc);
        part[j] = f.x + f.y;
    }

    __shared__ float sm[4][6];
#pragma unroll
    for (int i = 0; i < 6; i++) {
        float v = part[i];
#pragma unroll
        for (int o = 16; o; o >>= 1) v += __shfl_xor_sync(0xffffffffu, v, o);
        if ((t & 31) == 0) sm[t >> 5][i] = v;
    }
    __syncthreads();

    if (t == 0) {
        float sims[6];
#pragma unroll
        for (int j = 0; j < 6; j++)
            sims[j] = (sm[0][j] + sm[1][j] + sm[2][j] + sm[3][j]) * INV_T;
        float m = sims[0];
#pragma unroll
        for (int j = 1; j < 6; j++) m = fmaxf(m, sims[j]);
        float se = 0.f;
#pragma unroll
        for (int j = 0; j < 6; j++) se += expf(sims[j] - m);
        g_partial[l * NSAMP + n] = sims[0] - m - logf(se);
    }
}

// ---------------------------------------------------------------------------
// Deterministic 2-stage tail reduction.
// ---------------------------------------------------------------------------
__global__ __launch_bounds__(1024)
void mi_reduce1_kernel()
{
    const int t = threadIdx.x;
    float s = g_partial[blockIdx.x * 1024 + t];

    __shared__ float sm[32];
#pragma unroll
    for (int o = 16; o; o >>= 1) s += __shfl_xor_sync(0xffffffffu, s, o);
    if ((t & 31) == 0) sm[t >> 5] = s;
    __syncthreads();
    if (t < 32) {
        float v = sm[t];
#pragma unroll
        for (int o = 16; o; o >>= 1) v += __shfl_xor_sync(0xffffffffu, v, o);
        if (t == 0) g_stage[blockIdx.x] = v;
    }
}

__global__ __launch_bounds__(32)
void mi_reduce2_kernel(float* __restrict__ out)
{
    const int t = threadIdx.x;
    float v = (t < S1BLKS) ? g_stage[t] : 0.f;
#pragma unroll
    for (int o = 16; o; o >>= 1) v += __shfl_xor_sync(0xffffffffu, v, o);
    if (t == 0) out[0] = -v / (float)NPART;
}

extern "C" void kernel_launch(void* const* d_in, const int* in_sizes, int n_in,
                              void* d_out, int out_size)
{
    const float4* acts = (const float4*)d_in[0];
    const int* anchor_idx = (const int*)d_in[1];
    const int* pos_idx    = (const int*)d_in[2];
    const int* neg_idx    = (const int*)d_in[3];
    float* out = (float*)d_out;

    norm_kernel<<<NLAYERS * ROWS, 128>>>(acts);
    dim3 grid(NSAMP, NLAYERS);
    mi_pairs_kernel<<<grid, 128>>>(anchor_idx, pos_idx, neg_idx);
    mi_reduce1_kernel<<<S1BLKS, 1024>>>();
    mi_reduce2_kernel<<<1, 32>>>(out);
}